// round 5
// baseline (speedup 1.0000x reference)
#include <cuda_runtime.h>
#include <cstdint>

// real, pred: [128, 8192, 8] fp32. Row = 8 classes.
// loss = 1 - mean_over_rows( all_c( (pred>0.5) == real ) )

static constexpr int B = 128;
static constexpr int L = 8192;
static constexpr long long NROWS = (long long)B * L;      // 1,048,576
static constexpr int TPB = 256;
static constexpr int RPT = 1;                              // rows per thread
static constexpr int BLOCKS = (int)(NROWS / (TPB * RPT));  // 4096

__device__ unsigned int g_count = 0;   // correct-row count
__device__ unsigned int g_done  = 0;   // finished-block ticket counter

__device__ __forceinline__ int row_ok(float4 r0, float4 r1, float4 p0, float4 p1) {
    // real is exactly 0.0f or 1.0f; predicted label = (pred > 0.5f)
    bool ok =
        ((p0.x > 0.5f) == (r0.x != 0.0f)) &
        ((p0.y > 0.5f) == (r0.y != 0.0f)) &
        ((p0.z > 0.5f) == (r0.z != 0.0f)) &
        ((p0.w > 0.5f) == (r0.w != 0.0f)) &
        ((p1.x > 0.5f) == (r1.x != 0.0f)) &
        ((p1.y > 0.5f) == (r1.y != 0.0f)) &
        ((p1.z > 0.5f) == (r1.z != 0.0f)) &
        ((p1.w > 0.5f) == (r1.w != 0.0f));
    return (int)ok;
}

__global__ __launch_bounds__(TPB) void fused_kernel(
    const float4* __restrict__ real4, const float4* __restrict__ pred4,
    float* __restrict__ out)
{
    int row = blockIdx.x * TPB + threadIdx.x;

    // 4 independent LDG.128 front-batched (16 data regs -> high occupancy).
    // Default caching: 67MB working set stays warm in 126MB L2 across replays.
    float4 r0 = real4[2 * row + 0];
    float4 r1 = real4[2 * row + 1];
    float4 p0 = pred4[2 * row + 0];
    float4 p1 = pred4[2 * row + 1];

    int local = row_ok(r0, r1, p0, p1);

    // warp reduce
    local = __reduce_add_sync(0xFFFFFFFFu, local);

    __shared__ int smem[TPB / 32];
    if ((threadIdx.x & 31) == 0) smem[threadIdx.x >> 5] = local;
    __syncthreads();

    if (threadIdx.x == 0) {
        int t = 0;
#pragma unroll
        for (int w = 0; w < TPB / 32; w++) t += smem[w];
        atomicAdd(&g_count, (unsigned int)t);

        // last block finalizes and resets state for the next graph replay
        __threadfence();
        unsigned int ticket = atomicAdd(&g_done, 1u);
        if (ticket == (unsigned int)(BLOCKS - 1)) {
            unsigned int total = g_count;
            *out = 1.0f - (float)total * (1.0f / (float)NROWS);
            g_count = 0u;
            g_done = 0u;
        }
    }
}

extern "C" void kernel_launch(void* const* d_in, const int* in_sizes, int n_in,
                              void* d_out, int out_size) {
    const float4* real4 = (const float4*)d_in[0];
    const float4* pred4 = (const float4*)d_in[1];
    float* out = (float*)d_out;

    fused_kernel<<<BLOCKS, TPB>>>(real4, pred4, out);
}

// round 6
// speedup vs baseline: 1.1910x; 1.1910x over previous
#include <cuda_runtime.h>
#include <cstdint>

// real, pred: [128, 8192, 8] fp32. Row = 8 classes.
// loss = 1 - mean_over_rows( all_c( (pred>0.5) == real ) )

static constexpr int B = 128;
static constexpr int L = 8192;
static constexpr long long NROWS = (long long)B * L;      // 1,048,576
static constexpr int TPB = 256;
static constexpr int RPT = 2;                              // rows per thread
static constexpr int BLOCKS = (int)(NROWS / (TPB * RPT));  // 2048

__device__ unsigned int g_count = 0;   // correct-row count
__device__ unsigned int g_done  = 0;   // finished-block ticket counter

// Blackwell 256-bit global load: one LDG.E.256 fetches a full 8-float row.
__device__ __forceinline__ void ldg256(const float* p, float4& a, float4& b) {
    asm volatile("ld.global.v8.f32 {%0,%1,%2,%3,%4,%5,%6,%7}, [%8];"
        : "=f"(a.x), "=f"(a.y), "=f"(a.z), "=f"(a.w),
          "=f"(b.x), "=f"(b.y), "=f"(b.z), "=f"(b.w)
        : "l"(p));
}

__device__ __forceinline__ int row_ok(float4 r0, float4 r1, float4 p0, float4 p1) {
    // real is exactly 0.0f or 1.0f; predicted label = (pred > 0.5f)
    bool ok =
        ((p0.x > 0.5f) == (r0.x != 0.0f)) &
        ((p0.y > 0.5f) == (r0.y != 0.0f)) &
        ((p0.z > 0.5f) == (r0.z != 0.0f)) &
        ((p0.w > 0.5f) == (r0.w != 0.0f)) &
        ((p1.x > 0.5f) == (r1.x != 0.0f)) &
        ((p1.y > 0.5f) == (r1.y != 0.0f)) &
        ((p1.z > 0.5f) == (r1.z != 0.0f)) &
        ((p1.w > 0.5f) == (r1.w != 0.0f));
    return (int)ok;
}

__global__ __launch_bounds__(TPB) void fused_kernel(
    const float* __restrict__ real_, const float* __restrict__ pred_,
    float* __restrict__ out)
{
    const int stride = TPB * BLOCKS;               // rows per sweep
    int base = blockIdx.x * TPB + threadIdx.x;

    // Front-batch all 4 LDG.256 (2 rows x {real,pred}); 32 data regs.
    // Default caching: 67MB working set stays warm in 126MB L2 across replays.
    float4 r[RPT][2], p[RPT][2];
#pragma unroll
    for (int i = 0; i < RPT; i++) {
        int row = base + i * stride;
        ldg256(real_ + 8ll * row, r[i][0], r[i][1]);
        ldg256(pred_ + 8ll * row, p[i][0], p[i][1]);
    }

    int local = 0;
#pragma unroll
    for (int i = 0; i < RPT; i++)
        local += row_ok(r[i][0], r[i][1], p[i][0], p[i][1]);

    // warp reduce
    local = __reduce_add_sync(0xFFFFFFFFu, local);

    __shared__ int smem[TPB / 32];
    if ((threadIdx.x & 31) == 0) smem[threadIdx.x >> 5] = local;
    __syncthreads();

    if (threadIdx.x == 0) {
        int t = 0;
#pragma unroll
        for (int w = 0; w < TPB / 32; w++) t += smem[w];
        atomicAdd(&g_count, (unsigned int)t);

        // last block finalizes and resets state for the next graph replay
        __threadfence();
        unsigned int ticket = atomicAdd(&g_done, 1u);
        if (ticket == (unsigned int)(BLOCKS - 1)) {
            unsigned int total = g_count;
            *out = 1.0f - (float)total * (1.0f / (float)NROWS);
            g_count = 0u;
            g_done = 0u;
        }
    }
}

extern "C" void kernel_launch(void* const* d_in, const int* in_sizes, int n_in,
                              void* d_out, int out_size) {
    const float* real_ = (const float*)d_in[0];
    const float* pred_ = (const float*)d_in[1];
    float* out = (float*)d_out;

    fused_kernel<<<BLOCKS, TPB>>>(real_, pred_, out);
}